// round 3
// baseline (speedup 1.0000x reference)
#include <cuda_runtime.h>
#include <math.h>

// Qwen3VLMoeTextTopKRouter: logits = x @ W^T, softmax, top-8, renorm, dense scatter.
// Round 3 = round 2 resubmitted (infra failure, not a kernel failure):
// packed fp32x2 FMA (FFMA2) inner loop, A duplicated in smem so both
// packed operands come straight from LDS.128 with no packing MOVs.
// Accumulation order per logit unchanged (k-ascending fma chain) -> bitwise
// identical logits to round 1.

namespace {
constexpr int TOKENS = 32768;
constexpr int HID    = 2048;
constexpr int NE     = 128;
constexpr int TOPK   = 8;

constexpr int BM = 128;   // tokens per CTA
constexpr int BN = 128;   // experts (== NE, full width)
constexpr int BK = 16;
constexpr int NTHREADS = 256;
constexpr int LPAD = 4;   // logits smem row pad

// smem: A duplicated: [2][BK][2*BM] ; B: [2][BK][BN]
constexpr int A2_FLOATS = 2 * BK * (2 * BM);   // 8192
constexpr int B_FLOATS  = 2 * BK * BN;         // 4096
constexpr int GEMM_SMEM_FLOATS = A2_FLOATS + B_FLOATS;   // 12288 = 48 KB
constexpr int LOGIT_SMEM_FLOATS = BM * (BN + LPAD);      // 16896 = 66 KB
constexpr int SMEM_BYTES = (LOGIT_SMEM_FLOATS > GEMM_SMEM_FLOATS ?
                            LOGIT_SMEM_FLOATS : GEMM_SMEM_FLOATS) * 4; // 67584
}

#define FMA2(c, a, b) \
    asm("fma.rn.f32x2 %0, %1, %2, %3;" : "=l"(c) : "l"(a), "l"(b), "l"(c))

__global__ __launch_bounds__(NTHREADS, 2)
void router_kernel(const float* __restrict__ x, const float* __restrict__ w,
                   float* __restrict__ scores, float* __restrict__ idx_out,
                   int write_idx)
{
    extern __shared__ float smem[];
    float* As = smem;                 // [2][BK][2*BM]  duplicated token values
    float* Bs = smem + A2_FLOATS;     // [2][BK][BN]

    const int tid = threadIdx.x;
    const int tx  = tid & 15;         // expert-tile column group
    const int ty  = tid >> 4;         // token-tile row group
    const int m0  = blockIdx.x * BM;

    const int lrow = tid >> 2;        // 0..63
    const int lcol = tid & 3;         // 0..3 (float4 slot within BK=16 floats)

    const float* xg = x + (size_t)m0 * HID;

    // packed accumulators: cp[i][j] covers token (ty*8+i), experts (tx*8+2j, +2j+1)
    unsigned long long cp[8][4];
#pragma unroll
    for (int i = 0; i < 8; i++)
#pragma unroll
        for (int j = 0; j < 4; j++) cp[i][j] = 0ull;

    float4 ra[2], rb[2];

    auto store_tiles = [&](int buf) {
        float* A = As + buf * BK * (2 * BM);
        float* B = Bs + buf * BK * BN;
#pragma unroll
        for (int q = 0; q < 2; q++) {
            int r  = lrow + q * 64;
            int k4 = lcol * 4;
            // A duplicated: positions 2r, 2r+1 both = value (STS.64)
            *(float2*)&A[(k4 + 0) * (2 * BM) + 2 * r] = make_float2(ra[q].x, ra[q].x);
            *(float2*)&A[(k4 + 1) * (2 * BM) + 2 * r] = make_float2(ra[q].y, ra[q].y);
            *(float2*)&A[(k4 + 2) * (2 * BM) + 2 * r] = make_float2(ra[q].z, ra[q].z);
            *(float2*)&A[(k4 + 3) * (2 * BM) + 2 * r] = make_float2(ra[q].w, ra[q].w);
            B[(k4 + 0) * BN + r] = rb[q].x;
            B[(k4 + 1) * BN + r] = rb[q].y;
            B[(k4 + 2) * BN + r] = rb[q].z;
            B[(k4 + 3) * BN + r] = rb[q].w;
        }
    };

    // ---- prologue: load tile 0 ----
#pragma unroll
    for (int q = 0; q < 2; q++) {
        int r = lrow + q * 64;
        ra[q] = *(const float4*)(xg + (size_t)r * HID + lcol * 4);
        rb[q] = *(const float4*)(w  + (size_t)r * HID + lcol * 4);
    }
    store_tiles(0);
    __syncthreads();

    // ---- mainloop: double-buffered over K ----
    const int NT = HID / BK;  // 128
    for (int kt = 0; kt < NT; kt++) {
        const int cur = kt & 1;
        if (kt + 1 < NT) {
            const int koff = (kt + 1) * BK;
#pragma unroll
            for (int q = 0; q < 2; q++) {
                int r = lrow + q * 64;
                ra[q] = *(const float4*)(xg + (size_t)r * HID + koff + lcol * 4);
                rb[q] = *(const float4*)(w  + (size_t)r * HID + koff + lcol * 4);
            }
        }
        const float* A = As + cur * BK * (2 * BM);
        const float* B = Bs + cur * BK * BN;
#pragma unroll
        for (int kk = 0; kk < BK; kk++) {
            // a: duplicated pairs (a,a) straight from LDS.128
            unsigned long long ad[8], bp[4];
            {
                ulonglong2 t0 = *(const ulonglong2*)&A[kk * (2 * BM) + ty * 16];
                ulonglong2 t1 = *(const ulonglong2*)&A[kk * (2 * BM) + ty * 16 + 4];
                ulonglong2 t2 = *(const ulonglong2*)&A[kk * (2 * BM) + ty * 16 + 8];
                ulonglong2 t3 = *(const ulonglong2*)&A[kk * (2 * BM) + ty * 16 + 12];
                ad[0] = t0.x; ad[1] = t0.y; ad[2] = t1.x; ad[3] = t1.y;
                ad[4] = t2.x; ad[5] = t2.y; ad[6] = t3.x; ad[7] = t3.y;
                ulonglong2 u0 = *(const ulonglong2*)&B[kk * BN + tx * 8];
                ulonglong2 u1 = *(const ulonglong2*)&B[kk * BN + tx * 8 + 4];
                bp[0] = u0.x; bp[1] = u0.y; bp[2] = u1.x; bp[3] = u1.y;
            }
#pragma unroll
            for (int i = 0; i < 8; i++)
#pragma unroll
                for (int j = 0; j < 4; j++)
                    FMA2(cp[i][j], ad[i], bp[j]);
        }
        if (kt + 1 < NT) store_tiles(cur ^ 1);
        __syncthreads();
    }

    // ---- epilogue: logits -> smem (reuse), then per-token top-8 ----
    float* L = smem;  // [BM][BN + LPAD]
#pragma unroll
    for (int i = 0; i < 8; i++) {
        int row = ty * 8 + i;
#pragma unroll
        for (int j = 0; j < 4; j++) {
            *(float2*)&L[row * (BN + LPAD) + tx * 8 + 2 * j] =
                *(float2*)&cp[i][j];
        }
    }
    __syncthreads();

    const int warp = tid >> 5;
    const int lane = tid & 31;

    for (int tl = warp * 16; tl < warp * 16 + 16; tl++) {
        const float* row = &L[tl * (BN + LPAD)];
        float v[4];
#pragma unroll
        for (int k = 0; k < 4; k++) v[k] = row[lane + 32 * k];

        // 8 rounds of warp-wide argmax; tie-break = lower index (matches lax.top_k)
        float topv[8];
        int   topi[8];
#pragma unroll
        for (int r = 0; r < 8; r++) {
            float bv = -INFINITY;
            int   bi = 0x7fffffff;
#pragma unroll
            for (int k = 0; k < 4; k++) {
                if (v[k] > bv) { bv = v[k]; bi = lane + 32 * k; }
            }
#pragma unroll
            for (int off = 16; off > 0; off >>= 1) {
                float ov = __shfl_xor_sync(0xffffffffu, bv, off);
                int   oi = __shfl_xor_sync(0xffffffffu, bi, off);
                if (ov > bv || (ov == bv && oi < bi)) { bv = ov; bi = oi; }
            }
            topv[r] = bv;
            topi[r] = bi;
#pragma unroll
            for (int k = 0; k < 4; k++)
                if (lane + 32 * k == bi) v[k] = -INFINITY;
        }

        // renormalized top-k probs: exp(l - max) / sum_top8 exp(l - max)
        const float m = topv[0];
        float ev[8];
        float s = 0.f;
#pragma unroll
        for (int r = 0; r < 8; r++) { ev[r] = expf(topv[r] - m); s += ev[r]; }
        const float inv = 1.f / s;

        const int gt = m0 + tl;
        float* srow = scores + (size_t)gt * NE;
#pragma unroll
        for (int k = 0; k < 4; k++) {
            const int e = lane + 32 * k;
            float val = 0.f;
#pragma unroll
            for (int r = 0; r < 8; r++)
                if (topi[r] == e) val = ev[r] * inv;
            srow[e] = val;
        }
        if (write_idx && lane < TOPK)
            idx_out[(size_t)gt * TOPK + lane] = (float)topi[lane];
    }
}

extern "C" void kernel_launch(void* const* d_in, const int* in_sizes, int n_in,
                              void* d_out, int out_size)
{
    const float* x = (const float*)d_in[0];
    const float* w = (const float*)d_in[1];
    // defensive: detect swapped input order via element counts
    if (n_in >= 2 && in_sizes[0] == NE * HID && in_sizes[1] == TOKENS * HID) {
        x = (const float*)d_in[1];
        w = (const float*)d_in[0];
    }

    float* scores  = (float*)d_out;
    float* idx_out = scores + (size_t)TOKENS * NE;
    const int write_idx = (out_size >= TOKENS * NE + TOKENS * TOPK) ? 1 : 0;

    cudaFuncSetAttribute(router_kernel,
                         cudaFuncAttributeMaxDynamicSharedMemorySize, SMEM_BYTES);
    router_kernel<<<TOKENS / BM, NTHREADS, SMEM_BYTES>>>(x, w, scores, idx_out,
                                                         write_idx);
}